// round 4
// baseline (speedup 1.0000x reference)
#include <cuda_runtime.h>
#include <math.h>
#include <stdint.h>

// ---------------- problem constants ----------------
#define Bb      2
#define Ll      4096
#define DMODEL  1024
#define DINNER  2048
#define NHEADS  32
#define HEADDIM 64
#define DSTATE  128
#define DCONV   4
#define DIP     4384      // 2*DINNER + 2*DSTATE + NHEADS
#define CONVDIM 2304      // DINNER + 2*DSTATE
#define BL      (Bb*Ll)   // 8192
#define DOUT    1024

// ---------------- device scratch (no allocations allowed) ----------------
__device__ float g_zx [(size_t)BL * DIP];      // in_proj output
__device__ float g_xbc[(size_t)BL * CONVDIM];  // conv+silu out
__device__ float g_y  [(size_t)BL * DINNER];   // scan out / normed (tf32 bits)
__device__ float g_dt [BL * NHEADS];
__device__ float g_dA [BL * NHEADS];
__device__ float g_xc [(size_t)BL * DMODEL];   // x, tf32-rounded
__device__ float g_w1 [(size_t)DIP * DMODEL];  // in_proj_w, tf32-rounded
__device__ float g_w2 [(size_t)DOUT * DINNER]; // out_proj_w, tf32-rounded

__device__ __forceinline__ uint32_t f2tf(float f) {
    uint32_t r;
    asm("cvt.rna.tf32.f32 %0, %1;" : "=r"(r) : "f"(f));
    return r;
}

// =====================================================================
// Elementwise fp32 -> tf32(RNA)-rounded fp32 bits (float4 per thread)
// =====================================================================
__global__ __launch_bounds__(256) void cvt_tf32_kernel(
    const float* __restrict__ src, float* __restrict__ dst, int n4)
{
    const int i = blockIdx.x * blockDim.x + threadIdx.x;
    if (i >= n4) return;
    float4 v = ((const float4*)src)[i];
    uint4 u;
    u.x = f2tf(v.x); u.y = f2tf(v.y); u.z = f2tf(v.z); u.w = f2tf(v.w);
    ((uint4*)dst)[i] = u;
}

// =====================================================================
// TF32 tensor-core GEMM (NT), cp.async pipelined.
// C[M,N] = A[M,K] * B[N,K]^T. Inputs already tf32-rounded fp32 bits.
// 128x128 tile, BK=32, 256 threads (8 warps 2x4, warp tile 64x32),
// 2-stage cp.async double buffer, dynamic smem 2*2*128*36*4 = 73728 B.
// =====================================================================
#define GSTR 36            // smem row stride in floats (padded, conflict-free)
#define STAGE_F (128 * GSTR)          // floats per matrix per stage (4608)
#define STAGE_B (2 * STAGE_F * 4)     // bytes per stage (A+B) = 36864

__device__ __forceinline__ void mma_tf32(float c[4], const uint32_t a[4], const uint32_t b[2]) {
    asm volatile(
        "mma.sync.aligned.m16n8k8.row.col.f32.tf32.tf32.f32 "
        "{%0,%1,%2,%3}, {%4,%5,%6,%7}, {%8,%9}, {%0,%1,%2,%3};"
        : "+f"(c[0]), "+f"(c[1]), "+f"(c[2]), "+f"(c[3])
        : "r"(a[0]), "r"(a[1]), "r"(a[2]), "r"(a[3]), "r"(b[0]), "r"(b[1]));
}

__global__ __launch_bounds__(256, 2) void gemm_tf32_ca_kernel(
    const float* __restrict__ A, const float* __restrict__ Bw,
    float* __restrict__ C, int M, int N, int K)
{
    extern __shared__ float sm[];

    const int tid  = threadIdx.x;
    const int lane = tid & 31;
    const int warp = tid >> 5;
    const int wm = (warp >> 2) * 64;
    const int wn = (warp & 3) * 32;
    const int bm = blockIdx.y * 128;
    const int bn = blockIdx.x * 128;

    // cp.async staging: thread t -> row t>>1, 64B half (t&1), 4 x 16B chunks
    const int crow = tid >> 1;
    const int ccol = (tid & 1) * 16;          // float offset
    const float* Ag = A  + (size_t)(bm + crow) * K + ccol;
    const float* Bg = Bw + (size_t)(bn + crow) * K + ccol;
    const int bsz = ((bn + crow) < N) ? 16 : 0;   // zero-fill OOB B rows
    const uint32_t sbase = (uint32_t)__cvta_generic_to_shared(sm)
                         + (uint32_t)(crow * GSTR + ccol) * 4u;

#define G_ISSUE(kt, s) do {                                                   \
        const float* ag_ = Ag + (size_t)(kt) * 32;                            \
        const float* bg_ = Bg + (size_t)(kt) * 32;                            \
        uint32_t da_ = sbase + (s) * STAGE_B;                                 \
        uint32_t db_ = da_ + STAGE_F * 4;                                     \
        _Pragma("unroll")                                                     \
        for (int i_ = 0; i_ < 4; i_++)                                        \
            asm volatile("cp.async.cg.shared.global [%0], [%1], 16;"          \
                         :: "r"(da_ + i_ * 16), "l"(ag_ + i_ * 4));           \
        _Pragma("unroll")                                                     \
        for (int i_ = 0; i_ < 4; i_++)                                        \
            asm volatile("cp.async.cg.shared.global [%0], [%1], 16, %2;"      \
                         :: "r"(db_ + i_ * 16), "l"(bg_ + i_ * 4), "r"(bsz)); \
        asm volatile("cp.async.commit_group;");                               \
    } while (0)

    float acc[4][4][4];
#pragma unroll
    for (int mt = 0; mt < 4; mt++)
#pragma unroll
        for (int nt = 0; nt < 4; nt++)
#pragma unroll
            for (int i = 0; i < 4; i++) acc[mt][nt][i] = 0.f;

    const int KT = K / 32;
    G_ISSUE(0, 0);
    G_ISSUE(1, 1);

    for (int kt = 0; kt < KT; kt++) {
        asm volatile("cp.async.wait_group 1;");
        __syncthreads();

        const float* As = sm + (kt & 1) * (2 * STAGE_F);
        const float* Bs = As + STAGE_F;

#pragma unroll
        for (int ks = 0; ks < 4; ks++) {
            const int k = ks * 8 + (lane & 3);
            uint32_t af[4][4];
#pragma unroll
            for (int mt = 0; mt < 4; mt++) {
                const int m = wm + mt * 16 + (lane >> 2);
                af[mt][0] = __float_as_uint(As[m       * GSTR + k]);
                af[mt][1] = __float_as_uint(As[(m + 8) * GSTR + k]);
                af[mt][2] = __float_as_uint(As[m       * GSTR + k + 4]);
                af[mt][3] = __float_as_uint(As[(m + 8) * GSTR + k + 4]);
            }
            uint32_t bf[4][2];
#pragma unroll
            for (int nt = 0; nt < 4; nt++) {
                const int n = wn + nt * 8 + (lane >> 2);
                bf[nt][0] = __float_as_uint(Bs[n * GSTR + k]);
                bf[nt][1] = __float_as_uint(Bs[n * GSTR + k + 4]);
            }
#pragma unroll
            for (int mt = 0; mt < 4; mt++)
#pragma unroll
                for (int nt = 0; nt < 4; nt++)
                    mma_tf32(acc[mt][nt], af[mt], bf[nt]);
        }

        __syncthreads();
        if (kt + 2 < KT) G_ISSUE(kt + 2, kt & 1);
    }

#pragma unroll
    for (int mt = 0; mt < 4; mt++) {
        const int row = bm + wm + mt * 16 + (lane >> 2);
#pragma unroll
        for (int nt = 0; nt < 4; nt++) {
            const int col = bn + wn + nt * 8 + (lane & 3) * 2;
            if (col < N) {
                *(float2*)&C[(size_t)row * N + col]       = make_float2(acc[mt][nt][0], acc[mt][nt][1]);
                *(float2*)&C[(size_t)(row + 8) * N + col] = make_float2(acc[mt][nt][2], acc[mt][nt][3]);
            }
        }
    }
#undef G_ISSUE
}

// =====================================================================
// Depthwise causal conv (taps=4) + bias + SiLU over CONVDIM channels
// =====================================================================
__global__ __launch_bounds__(256) void conv_silu_kernel(
    const float* __restrict__ conv_w, const float* __restrict__ conv_b)
{
    const int idx = blockIdx.x * blockDim.x + threadIdx.x;
    const int total = BL * CONVDIM;
    if (idx >= total) return;
    const int c  = idx % CONVDIM;
    const int bl = idx / CONVDIM;
    const int l  = bl & (Ll - 1);

    float acc = conv_b[c];
    const float* col = g_zx + (size_t)bl * DIP + DINNER + c;
#pragma unroll
    for (int j = 0; j < 4; j++) {
        const int ls = l - 3 + j;
        if (ls >= 0)
            acc = fmaf(col[(long)(j - 3) * DIP], conv_w[c * 4 + j], acc);
    }
    g_xbc[idx] = acc / (1.f + expf(-acc));
}

// =====================================================================
// dt: softplus(dt_raw + bias); dA = exp(dt * (-exp(A_log)))
// =====================================================================
__global__ __launch_bounds__(256) void dt_kernel(
    const float* __restrict__ dt_bias, const float* __restrict__ A_log)
{
    const int idx = blockIdx.x * blockDim.x + threadIdx.x;
    if (idx >= BL * NHEADS) return;
    const int h  = idx & (NHEADS - 1);
    const int bl = idx >> 5;
    float raw = g_zx[(size_t)bl * DIP + DINNER + CONVDIM + h] + dt_bias[h];
    float dt = (raw > 20.f) ? raw : log1pf(expf(raw));
    float A = -expf(A_log[h]);
    g_dt[idx] = dt;
    g_dA[idx] = expf(dt * A);
}

// =====================================================================
// Chunked deep-pipelined selective scan (unchanged from R3).
// =====================================================================
#define DCH 8

__global__ __launch_bounds__(256) void scan_kernel(const float* __restrict__ Dp)
{
    const int bx = blockIdx.x;
    const int bh = bx >> 1;
    const int ph = bx & 1;
    const int b = bh >> 5;
    const int h = bh & 31;
    const int tid = threadIdx.x;
    const int p  = tid >> 3;
    const int ns = tid & 7;

    __shared__ float s_bc[2][DCH][256];
    __shared__ float s_x [2][DCH][32];
    __shared__ float s_dt[2][DCH];
    __shared__ float s_dA[2][DCH];

    float hs[16];
#pragma unroll
    for (int i = 0; i < 16; i++) hs[i] = 0.f;

    const float* base = g_xbc + (size_t)b * Ll * CONVDIM;
    const float* dtp  = g_dt  + (size_t)b * Ll * NHEADS + h;
    const float* dAp  = g_dA  + (size_t)b * Ll * NHEADS + h;
    const float Dh = Dp[h];
    const int xoff = h * 64 + ph * 32;
    float* yrow = g_y + (size_t)b * Ll * DINNER + xoff + p;

#pragma unroll
    for (int d = 0; d < DCH; d++)
        s_bc[0][d][tid] = base[(size_t)d * CONVDIM + DINNER + tid];
    if (tid < 32) {
#pragma unroll
        for (int d = 0; d < DCH; d++)
            s_x[0][d][tid] = base[(size_t)d * CONVDIM + xoff + tid];
    }
    if (tid < DCH)               s_dt[0][tid]       = dtp[(size_t)tid * NHEADS];
    else if (tid < 2 * DCH)      s_dA[0][tid - DCH] = dAp[(size_t)(tid - DCH) * NHEADS];

    float pf[DCH], pfx[DCH];
    float pfdt = 0.f, pfdA = 0.f;
#pragma unroll
    for (int d = 0; d < DCH; d++)
        pf[d] = base[(size_t)(DCH + d) * CONVDIM + DINNER + tid];
    if (tid < 32) {
#pragma unroll
        for (int d = 0; d < DCH; d++)
            pfx[d] = base[(size_t)(DCH + d) * CONVDIM + xoff + tid];
    }
    if (tid < DCH)               pfdt = dtp[(size_t)(DCH + tid) * NHEADS];
    else if (tid < 2 * DCH)      pfdA = dAp[(size_t)(DCH + tid - DCH) * NHEADS];
    __syncthreads();

    const int NCH = Ll / DCH;
    int buf = 0;
    for (int ci = 0; ci < NCH; ci++) {
        if (ci + 1 < NCH) {
#pragma unroll
            for (int d = 0; d < DCH; d++) s_bc[buf ^ 1][d][tid] = pf[d];
            if (tid < 32) {
#pragma unroll
                for (int d = 0; d < DCH; d++) s_x[buf ^ 1][d][tid] = pfx[d];
            }
            if (tid < DCH)          s_dt[buf ^ 1][tid]       = pfdt;
            else if (tid < 2 * DCH) s_dA[buf ^ 1][tid - DCH] = pfdA;
        }
        if (ci + 2 < NCH) {
            const size_t t2 = (size_t)(ci + 2) * DCH;
#pragma unroll
            for (int d = 0; d < DCH; d++)
                pf[d] = base[(t2 + d) * CONVDIM + DINNER + tid];
            if (tid < 32) {
#pragma unroll
                for (int d = 0; d < DCH; d++)
                    pfx[d] = base[(t2 + d) * CONVDIM + xoff + tid];
            }
            if (tid < DCH)          pfdt = dtp[(t2 + tid) * NHEADS];
            else if (tid < 2 * DCH) pfdA = dAp[(t2 + tid - DCH) * NHEADS];
        }
        const int t0 = ci * DCH;
#pragma unroll
        for (int d = 0; d < DCH; d++) {
            const float cdt = s_dt[buf][d];
            const float cdA = s_dA[buf][d];
            const float xp  = s_x[buf][d][p];
            const float kx  = cdt * xp;
            const float* Bp = &s_bc[buf][d][ns * 16];
            const float* Cp = &s_bc[buf][d][128 + ns * 16];

            float acc = 0.f;
#pragma unroll
            for (int jj = 0; jj < 4; jj++) {
                float4 Bv = *(const float4*)(Bp + jj * 4);
                float4 Cv = *(const float4*)(Cp + jj * 4);
                float h0, h1, h2, h3;
                h0 = fmaf(hs[jj*4+0], cdA, kx * Bv.x); hs[jj*4+0] = h0; acc = fmaf(h0, Cv.x, acc);
                h1 = fmaf(hs[jj*4+1], cdA, kx * Bv.y); hs[jj*4+1] = h1; acc = fmaf(h1, Cv.y, acc);
                h2 = fmaf(hs[jj*4+2], cdA, kx * Bv.z); hs[jj*4+2] = h2; acc = fmaf(h2, Cv.z, acc);
                h3 = fmaf(hs[jj*4+3], cdA, kx * Bv.w); hs[jj*4+3] = h3; acc = fmaf(h3, Cv.w, acc);
            }
            acc += __shfl_xor_sync(0xffffffffu, acc, 1);
            acc += __shfl_xor_sync(0xffffffffu, acc, 2);
            acc += __shfl_xor_sync(0xffffffffu, acc, 4);
            if (ns == 0)
                yrow[(size_t)(t0 + d) * DINNER] = acc + Dh * xp;
        }
        __syncthreads();
        buf ^= 1;
    }
}

// =====================================================================
// y = y * silu(z); RMSnorm; store tf32-rounded (feeds GEMM2 directly)
// =====================================================================
__global__ __launch_bounds__(256) void gatenorm_kernel(const float* __restrict__ norm_w)
{
    const int row = blockIdx.x;
    const float* zrow = g_zx + (size_t)row * DIP;
    float* yrow = g_y + (size_t)row * DINNER;

    float v[8];
    float ss = 0.f;
#pragma unroll
    for (int i = 0; i < 8; i++) {
        const int c = threadIdx.x + i * 256;
        float d = yrow[c];
        float z = zrow[c];
        float g = d * (z / (1.f + expf(-z)));
        v[i] = g;
        ss = fmaf(g, g, ss);
    }
#pragma unroll
    for (int o = 16; o; o >>= 1) ss += __shfl_xor_sync(0xffffffffu, ss, o);

    __shared__ float red[8];
    if ((threadIdx.x & 31) == 0) red[threadIdx.x >> 5] = ss;
    __syncthreads();
    float tot = 0.f;
#pragma unroll
    for (int w = 0; w < 8; w++) tot += red[w];
    const float scale = rsqrtf(tot * (1.f / (float)DINNER) + 1e-5f);

#pragma unroll
    for (int i = 0; i < 8; i++) {
        const int c = threadIdx.x + i * 256;
        yrow[c] = __uint_as_float(f2tf(v[i] * scale * norm_w[c]));
    }
}

// =====================================================================
// launch
// =====================================================================
extern "C" void kernel_launch(void* const* d_in, const int* in_sizes, int n_in,
                              void* d_out, int out_size)
{
    const float* x          = (const float*)d_in[0];
    const float* in_proj_w  = (const float*)d_in[1];
    const float* conv_w     = (const float*)d_in[2];
    const float* conv_b     = (const float*)d_in[3];
    const float* dt_bias    = (const float*)d_in[4];
    const float* A_log      = (const float*)d_in[5];
    const float* Dp         = (const float*)d_in[6];
    const float* norm_w     = (const float*)d_in[7];
    const float* out_proj_w = (const float*)d_in[8];
    float* out = (float*)d_out;

    float *zx, *yb, *xc, *w1, *w2;
    cudaGetSymbolAddress((void**)&zx, g_zx);
    cudaGetSymbolAddress((void**)&yb, g_y);
    cudaGetSymbolAddress((void**)&xc, g_xc);
    cudaGetSymbolAddress((void**)&w1, g_w1);
    cudaGetSymbolAddress((void**)&w2, g_w2);

    cudaFuncSetAttribute(gemm_tf32_ca_kernel,
                         cudaFuncAttributeMaxDynamicSharedMemorySize, 2 * STAGE_B);

    // 0) pre-round inputs to tf32 (RNA)
    {
        int n4;
        n4 = (BL * DMODEL) / 4;
        cvt_tf32_kernel<<<(n4 + 255) / 256, 256>>>(x, xc, n4);
        n4 = (DIP * DMODEL) / 4;
        cvt_tf32_kernel<<<(n4 + 255) / 256, 256>>>(in_proj_w, w1, n4);
        n4 = (DOUT * DINNER) / 4;
        cvt_tf32_kernel<<<(n4 + 255) / 256, 256>>>(out_proj_w, w2, n4);
    }
    // 1) in_proj GEMM: [8192,1024] x [4384,1024]^T -> g_zx
    {
        dim3 grid((DIP + 127) / 128, BL / 128);
        gemm_tf32_ca_kernel<<<grid, 256, 2 * STAGE_B>>>(xc, w1, zx, BL, DIP, DMODEL);
    }
    // 2) depthwise conv + silu
    {
        const int total = BL * CONVDIM;
        conv_silu_kernel<<<(total + 255) / 256, 256>>>(conv_w, conv_b);
    }
    // 3) dt softplus + dA
    dt_kernel<<<(BL * NHEADS) / 256, 256>>>(dt_bias, A_log);
    // 4) chunked pipelined scan
    scan_kernel<<<2 * Bb * NHEADS, 256>>>(Dp);
    // 5) gate + RMSnorm (writes tf32-rounded)
    gatenorm_kernel<<<BL, 256>>>(norm_w);
    // 6) out_proj GEMM: [8192,2048] x [1024,2048]^T -> d_out
    {
        dim3 grid(DOUT / 128, BL / 128);
        gemm_tf32_ca_kernel<<<grid, 256, 2 * STAGE_B>>>(yb, w2, out, BL, DOUT, DINNER);
    }
}

// round 5
// speedup vs baseline: 1.5495x; 1.5495x over previous
#include <cuda_runtime.h>
#include <math.h>
#include <stdint.h>

// ---------------- problem constants ----------------
#define Bb      2
#define Ll      4096
#define DMODEL  1024
#define DINNER  2048
#define NHEADS  32
#define HEADDIM 64
#define DSTATE  128
#define DCONV   4
#define DIP     4384      // 2*DINNER + 2*DSTATE + NHEADS
#define CONVDIM 2304      // DINNER + 2*DSTATE
#define BL      (Bb*Ll)   // 8192
#define DOUT    1024
#define NQ      4         // DSTATE split factor in the scan

// ---------------- device scratch (no allocations allowed) ----------------
__device__ float g_zx [(size_t)BL * DIP];       // in_proj output
__device__ float g_xbc[(size_t)BL * CONVDIM];   // conv+silu out
__device__ float g_y  [(size_t)BL * DINNER];    // normed out (tf32 bits) -> GEMM2
__device__ float g_yp [(size_t)NQ * BL * DINNER]; // scan partial sums (per n-quarter)
__device__ float g_dt [BL * NHEADS];
__device__ float g_dA [BL * NHEADS];
__device__ float g_xc [(size_t)BL * DMODEL];    // x, tf32-rounded
__device__ float g_w1 [(size_t)DIP * DMODEL];   // in_proj_w, tf32-rounded
__device__ float g_w2 [(size_t)DOUT * DINNER];  // out_proj_w, tf32-rounded

__device__ __forceinline__ uint32_t f2tf(float f) {
    uint32_t r;
    asm("cvt.rna.tf32.f32 %0, %1;" : "=r"(r) : "f"(f));
    return r;
}

// =====================================================================
// Elementwise fp32 -> tf32(RNA)-rounded fp32 bits
// =====================================================================
__global__ __launch_bounds__(256) void cvt_tf32_kernel(
    const float* __restrict__ src, float* __restrict__ dst, int n4)
{
    const int i = blockIdx.x * blockDim.x + threadIdx.x;
    if (i >= n4) return;
    float4 v = ((const float4*)src)[i];
    uint4 u;
    u.x = f2tf(v.x); u.y = f2tf(v.y); u.z = f2tf(v.z); u.w = f2tf(v.w);
    ((uint4*)dst)[i] = u;
}

// =====================================================================
// TF32 tensor-core GEMM (NT), cp.async pipelined (unchanged from R4).
// =====================================================================
#define GSTR 36
#define STAGE_F (128 * GSTR)
#define STAGE_B (2 * STAGE_F * 4)

__device__ __forceinline__ void mma_tf32(float c[4], const uint32_t a[4], const uint32_t b[2]) {
    asm volatile(
        "mma.sync.aligned.m16n8k8.row.col.f32.tf32.tf32.f32 "
        "{%0,%1,%2,%3}, {%4,%5,%6,%7}, {%8,%9}, {%0,%1,%2,%3};"
        : "+f"(c[0]), "+f"(c[1]), "+f"(c[2]), "+f"(c[3])
        : "r"(a[0]), "r"(a[1]), "r"(a[2]), "r"(a[3]), "r"(b[0]), "r"(b[1]));
}

__global__ __launch_bounds__(256, 2) void gemm_tf32_ca_kernel(
    const float* __restrict__ A, const float* __restrict__ Bw,
    float* __restrict__ C, int M, int N, int K)
{
    extern __shared__ float sm[];

    const int tid  = threadIdx.x;
    const int lane = tid & 31;
    const int warp = tid >> 5;
    const int wm = (warp >> 2) * 64;
    const int wn = (warp & 3) * 32;
    const int bm = blockIdx.y * 128;
    const int bn = blockIdx.x * 128;

    const int crow = tid >> 1;
    const int ccol = (tid & 1) * 16;
    const float* Ag = A  + (size_t)(bm + crow) * K + ccol;
    const float* Bg = Bw + (size_t)(bn + crow) * K + ccol;
    const int bsz = ((bn + crow) < N) ? 16 : 0;
    const uint32_t sbase = (uint32_t)__cvta_generic_to_shared(sm)
                         + (uint32_t)(crow * GSTR + ccol) * 4u;

#define G_ISSUE(kt, s) do {                                                   \
        const float* ag_ = Ag + (size_t)(kt) * 32;                            \
        const float* bg_ = Bg + (size_t)(kt) * 32;                            \
        uint32_t da_ = sbase + (s) * STAGE_B;                                 \
        uint32_t db_ = da_ + STAGE_F * 4;                                     \
        _Pragma("unroll")                                                     \
        for (int i_ = 0; i_ < 4; i_++)                                        \
            asm volatile("cp.async.cg.shared.global [%0], [%1], 16;"          \
                         :: "r"(da_ + i_ * 16), "l"(ag_ + i_ * 4));           \
        _Pragma("unroll")                                                     \
        for (int i_ = 0; i_ < 4; i_++)                                        \
            asm volatile("cp.async.cg.shared.global [%0], [%1], 16, %2;"      \
                         :: "r"(db_ + i_ * 16), "l"(bg_ + i_ * 4), "r"(bsz)); \
        asm volatile("cp.async.commit_group;");                               \
    } while (0)

    float acc[4][4][4];
#pragma unroll
    for (int mt = 0; mt < 4; mt++)
#pragma unroll
        for (int nt = 0; nt < 4; nt++)
#pragma unroll
            for (int i = 0; i < 4; i++) acc[mt][nt][i] = 0.f;

    const int KT = K / 32;
    G_ISSUE(0, 0);
    G_ISSUE(1, 1);

    for (int kt = 0; kt < KT; kt++) {
        asm volatile("cp.async.wait_group 1;");
        __syncthreads();

        const float* As = sm + (kt & 1) * (2 * STAGE_F);
        const float* Bs = As + STAGE_F;

#pragma unroll
        for (int ks = 0; ks < 4; ks++) {
            const int k = ks * 8 + (lane & 3);
            uint32_t af[4][4];
#pragma unroll
            for (int mt = 0; mt < 4; mt++) {
                const int m = wm + mt * 16 + (lane >> 2);
                af[mt][0] = __float_as_uint(As[m       * GSTR + k]);
                af[mt][1] = __float_as_uint(As[(m + 8) * GSTR + k]);
                af[mt][2] = __float_as_uint(As[m       * GSTR + k + 4]);
                af[mt][3] = __float_as_uint(As[(m + 8) * GSTR + k + 4]);
            }
            uint32_t bf[4][2];
#pragma unroll
            for (int nt = 0; nt < 4; nt++) {
                const int n = wn + nt * 8 + (lane >> 2);
                bf[nt][0] = __float_as_uint(Bs[n * GSTR + k]);
                bf[nt][1] = __float_as_uint(Bs[n * GSTR + k + 4]);
            }
#pragma unroll
            for (int mt = 0; mt < 4; mt++)
#pragma unroll
                for (int nt = 0; nt < 4; nt++)
                    mma_tf32(acc[mt][nt], af[mt], bf[nt]);
        }

        __syncthreads();
        if (kt + 2 < KT) G_ISSUE(kt + 2, kt & 1);
    }

#pragma unroll
    for (int mt = 0; mt < 4; mt++) {
        const int row = bm + wm + mt * 16 + (lane >> 2);
#pragma unroll
        for (int nt = 0; nt < 4; nt++) {
            const int col = bn + wn + nt * 8 + (lane & 3) * 2;
            if (col < N) {
                *(float2*)&C[(size_t)row * N + col]       = make_float2(acc[mt][nt][0], acc[mt][nt][1]);
                *(float2*)&C[(size_t)(row + 8) * N + col] = make_float2(acc[mt][nt][2], acc[mt][nt][3]);
            }
        }
    }
#undef G_ISSUE
}

// =====================================================================
// Depthwise causal conv (taps=4) + bias + SiLU
// =====================================================================
__global__ __launch_bounds__(256) void conv_silu_kernel(
    const float* __restrict__ conv_w, const float* __restrict__ conv_b)
{
    const int idx = blockIdx.x * blockDim.x + threadIdx.x;
    const int total = BL * CONVDIM;
    if (idx >= total) return;
    const int c  = idx % CONVDIM;
    const int bl = idx / CONVDIM;
    const int l  = bl & (Ll - 1);

    float acc = conv_b[c];
    const float* col = g_zx + (size_t)bl * DIP + DINNER + c;
#pragma unroll
    for (int j = 0; j < 4; j++) {
        const int ls = l - 3 + j;
        if (ls >= 0)
            acc = fmaf(col[(long)(j - 3) * DIP], conv_w[c * 4 + j], acc);
    }
    g_xbc[idx] = acc / (1.f + expf(-acc));
}

// =====================================================================
// dt: softplus(dt_raw + bias); dA = exp(dt * (-exp(A_log)))
// =====================================================================
__global__ __launch_bounds__(256) void dt_kernel(
    const float* __restrict__ dt_bias, const float* __restrict__ A_log)
{
    const int idx = blockIdx.x * blockDim.x + threadIdx.x;
    if (idx >= BL * NHEADS) return;
    const int h  = idx & (NHEADS - 1);
    const int bl = idx >> 5;
    float raw = g_zx[(size_t)bl * DIP + DINNER + CONVDIM + h] + dt_bias[h];
    float dt = (raw > 20.f) ? raw : log1pf(expf(raw));
    float A = -expf(A_log[h]);
    g_dt[idx] = dt;
    g_dA[idx] = expf(dt * A);
}

// =====================================================================
// Selective scan, state-split x4, shuffle-free.
// Block = (b, h, phalf, nquarter): 512 blocks, 256 threads.
// Thread (p = tid>>3 in [0,32), ns = tid&7) holds 4 states of its
// 32-state quarter. Per-step partials -> smem; one cooperative
// reduction per 8-step chunk (256 thr = 8d x 32p). Partial y per
// quarter goes to g_yp[nq]; gatenorm sums the quarters.
// =====================================================================
#define DCH 8

__global__ __launch_bounds__(256) void scan_kernel(const float* __restrict__ Dp)
{
    const int bx = blockIdx.x;
    const int nq = bx & 3;
    const int ph = (bx >> 2) & 1;
    const int h  = (bx >> 3) & 31;
    const int b  = bx >> 8;
    const int tid = threadIdx.x;
    const int p  = tid >> 3;     // 0..31
    const int ns = tid & 7;      // 0..7

    __shared__ float s_bc[2][DCH][64];     // [0:32)=B quarter, [32:64)=C quarter
    __shared__ float s_x [2][DCH][32];
    __shared__ float s_dt[2][DCH];
    __shared__ float s_dA[2][DCH];
    __shared__ float s_part[DCH][32][9];   // per-step partial sums

    float hs[4] = {0.f, 0.f, 0.f, 0.f};

    const float* base = g_xbc + (size_t)b * Ll * CONVDIM;
    const float* dtp  = g_dt  + (size_t)b * Ll * NHEADS + h;
    const float* dAp  = g_dA  + (size_t)b * Ll * NHEADS + h;
    const float Dh = Dp[h];
    const int xoff = h * 64 + ph * 32;

    // staging indices: bc -> thread covers (d0, c) and (d0+4, c)
    const int c  = tid & 63;
    const int d0 = tid >> 6;                      // 0..3
    const int gcol = DINNER + nq * 32 + (c < 32 ? c : DSTATE + c - 32);
    const int dx = tid >> 5;                      // 0..7 (x staging)
    const int px = tid & 31;

    // reduction indices: thread -> (dr, pr)
    const int dr = tid >> 5;                      // 0..7
    const int pr = tid & 31;                      // 0..31

    // ---- prologue: chunk 0 straight to smem ----
    s_bc[0][d0    ][c] = base[(size_t)d0       * CONVDIM + gcol];
    s_bc[0][d0 + 4][c] = base[(size_t)(d0 + 4) * CONVDIM + gcol];
    s_x[0][dx][px]     = base[(size_t)dx * CONVDIM + xoff + px];
    if (tid < DCH)          s_dt[0][tid]     = dtp[(size_t)tid * NHEADS];
    else if (tid < 2 * DCH) s_dA[0][tid - 8] = dAp[(size_t)(tid - 8) * NHEADS];

    // ---- prefetch chunk 1 into registers ----
    float pf0 = base[(size_t)(DCH + d0    ) * CONVDIM + gcol];
    float pf1 = base[(size_t)(DCH + d0 + 4) * CONVDIM + gcol];
    float pfx = base[(size_t)(DCH + dx) * CONVDIM + xoff + px];
    float pfdt = 0.f, pfdA = 0.f;
    if (tid < DCH)          pfdt = dtp[(size_t)(DCH + tid) * NHEADS];
    else if (tid < 2 * DCH) pfdA = dAp[(size_t)(DCH + tid - 8) * NHEADS];
    __syncthreads();

    float* yq = g_yp + (size_t)nq * BL * DINNER + (size_t)b * Ll * DINNER + xoff + pr;

    const int NCH = Ll / DCH;
    int buf = 0;
    for (int ci = 0; ci < NCH; ci++) {
        // 1) publish chunk ci+1 into the idle buffer
        if (ci + 1 < NCH) {
            s_bc[buf ^ 1][d0    ][c] = pf0;
            s_bc[buf ^ 1][d0 + 4][c] = pf1;
            s_x[buf ^ 1][dx][px]     = pfx;
            if (tid < DCH)          s_dt[buf ^ 1][tid]     = pfdt;
            else if (tid < 2 * DCH) s_dA[buf ^ 1][tid - 8] = pfdA;
        }
        // 2) issue loads for chunk ci+2
        if (ci + 2 < NCH) {
            const size_t t2 = (size_t)(ci + 2) * DCH;
            pf0 = base[(t2 + d0    ) * CONVDIM + gcol];
            pf1 = base[(t2 + d0 + 4) * CONVDIM + gcol];
            pfx = base[(t2 + dx) * CONVDIM + xoff + px];
            if (tid < DCH)          pfdt = dtp[(t2 + tid) * NHEADS];
            else if (tid < 2 * DCH) pfdA = dAp[(t2 + tid - 8) * NHEADS];
        }
        // 3) 8 scan steps from the current buffer
#pragma unroll
        for (int d = 0; d < DCH; d++) {
            const float cdt = s_dt[buf][d];
            const float cdA = s_dA[buf][d];
            const float kx  = cdt * s_x[buf][d][p];
            const float4 Bv = *(const float4*)&s_bc[buf][d][ns * 4];
            const float4 Cv = *(const float4*)&s_bc[buf][d][32 + ns * 4];
            float a0, a1;
            hs[0] = fmaf(hs[0], cdA, kx * Bv.x); a0 = hs[0] * Cv.x;
            hs[1] = fmaf(hs[1], cdA, kx * Bv.y); a0 = fmaf(hs[1], Cv.y, a0);
            hs[2] = fmaf(hs[2], cdA, kx * Bv.z); a1 = hs[2] * Cv.z;
            hs[3] = fmaf(hs[3], cdA, kx * Bv.w); a1 = fmaf(hs[3], Cv.w, a1);
            s_part[d][p][ns] = a0 + a1;
        }
        __syncthreads();   // s_part + published buffer complete

        // 4) cooperative reduction: thread (dr, pr) sums 8 partials
        {
            const float* sp = s_part[dr][pr];
            float sum = ((sp[0] + sp[1]) + (sp[2] + sp[3]))
                      + ((sp[4] + sp[5]) + (sp[6] + sp[7]));
            if (nq == 0) sum = fmaf(Dh, s_x[buf][dr][pr], sum);
            yq[(size_t)(ci * DCH + dr) * DINNER] = sum;
        }
        __syncthreads();   // protect s_part / s_x before next chunk
        buf ^= 1;
    }
}

// =====================================================================
// y = (sum of 4 scan partials) * silu(z); RMSnorm; store tf32-rounded
// =====================================================================
__global__ __launch_bounds__(256) void gatenorm_kernel(const float* __restrict__ norm_w)
{
    const int row = blockIdx.x;
    const float* zrow = g_zx + (size_t)row * DIP;
    const float* y0 = g_yp + (size_t)row * DINNER;
    const float* y1 = y0 + (size_t)BL * DINNER;
    const float* y2 = y1 + (size_t)BL * DINNER;
    const float* y3 = y2 + (size_t)BL * DINNER;
    float* yrow = g_y + (size_t)row * DINNER;

    float v[8];
    float ss = 0.f;
#pragma unroll
    for (int i = 0; i < 8; i++) {
        const int c = threadIdx.x + i * 256;
        float d = (y0[c] + y1[c]) + (y2[c] + y3[c]);
        float z = zrow[c];
        float g = d * (z / (1.f + expf(-z)));
        v[i] = g;
        ss = fmaf(g, g, ss);
    }
#pragma unroll
    for (int o = 16; o; o >>= 1) ss += __shfl_xor_sync(0xffffffffu, ss, o);

    __shared__ float red[8];
    if ((threadIdx.x & 31) == 0) red[threadIdx.x >> 5] = ss;
    __syncthreads();
    float tot = 0.f;
#pragma unroll
    for (int w = 0; w < 8; w++) tot += red[w];
    const float scale = rsqrtf(tot * (1.f / (float)DINNER) + 1e-5f);

#pragma unroll
    for (int i = 0; i < 8; i++) {
        const int c = threadIdx.x + i * 256;
        yrow[c] = __uint_as_float(f2tf(v[i] * scale * norm_w[c]));
    }
}

// =====================================================================
// launch
// =====================================================================
extern "C" void kernel_launch(void* const* d_in, const int* in_sizes, int n_in,
                              void* d_out, int out_size)
{
    const float* x          = (const float*)d_in[0];
    const float* in_proj_w  = (const float*)d_in[1];
    const float* conv_w     = (const float*)d_in[2];
    const float* conv_b     = (const float*)d_in[3];
    const float* dt_bias    = (const float*)d_in[4];
    const float* A_log      = (const float*)d_in[5];
    const float* Dp         = (const float*)d_in[6];
    const float* norm_w     = (const float*)d_in[7];
    const float* out_proj_w = (const float*)d_in[8];
    float* out = (float*)d_out;

    float *zx, *yb, *xc, *w1, *w2;
    cudaGetSymbolAddress((void**)&zx, g_zx);
    cudaGetSymbolAddress((void**)&yb, g_y);
    cudaGetSymbolAddress((void**)&xc, g_xc);
    cudaGetSymbolAddress((void**)&w1, g_w1);
    cudaGetSymbolAddress((void**)&w2, g_w2);

    cudaFuncSetAttribute(gemm_tf32_ca_kernel,
                         cudaFuncAttributeMaxDynamicSharedMemorySize, 2 * STAGE_B);

    // 0) pre-round GEMM inputs to tf32 (RNA)
    {
        int n4;
        n4 = (BL * DMODEL) / 4;
        cvt_tf32_kernel<<<(n4 + 255) / 256, 256>>>(x, xc, n4);
        n4 = (DIP * DMODEL) / 4;
        cvt_tf32_kernel<<<(n4 + 255) / 256, 256>>>(in_proj_w, w1, n4);
        n4 = (DOUT * DINNER) / 4;
        cvt_tf32_kernel<<<(n4 + 255) / 256, 256>>>(out_proj_w, w2, n4);
    }
    // 1) in_proj GEMM
    {
        dim3 grid((DIP + 127) / 128, BL / 128);
        gemm_tf32_ca_kernel<<<grid, 256, 2 * STAGE_B>>>(xc, w1, zx, BL, DIP, DMODEL);
    }
    // 2) depthwise conv + silu
    {
        const int total = BL * CONVDIM;
        conv_silu_kernel<<<(total + 255) / 256, 256>>>(conv_w, conv_b);
    }
    // 3) dt softplus + dA
    dt_kernel<<<(BL * NHEADS) / 256, 256>>>(dt_bias, A_log);
    // 4) state-split scan (512 blocks)
    scan_kernel<<<NQ * 2 * Bb * NHEADS, 256>>>(Dp);
    // 5) gate + RMSnorm (sums 4 partials, writes tf32-rounded)
    gatenorm_kernel<<<BL, 256>>>(norm_w);
    // 6) out_proj GEMM
    {
        dim3 grid(DOUT / 128, BL / 128);
        gemm_tf32_ca_kernel<<<grid, 256, 2 * STAGE_B>>>(yb, w2, out, BL, DOUT, DINNER);
    }
}